// round 1
// baseline (speedup 1.0000x reference)
#include <cuda_runtime.h>
#include <math.h>

#define BB 16
#define TT 750
#define FF 4096
#define CC 20
#define KTOP 93
#define ROWS (BB*TT)

// ---- output layout (flattened tuple, reference return order) ----
#define OFF_SACT 0
#define OFF_SBKG (BB*CC)
#define OFF_FACT (2*BB*CC)
#define OFF_FBKG (OFF_FACT + BB*KTOP*FF)
#define OFF_FEAT (OFF_FBKG + BB*KTOP*FF)
#define OFF_CSM  (OFF_FEAT + ROWS*FF)

// ---- scratch (no allocations allowed -> device globals) ----
__device__ float g_cas[ROWS*CC];
__device__ float g_mag[ROWS];
__device__ int   g_idx_act[BB*KTOP];
__device__ int   g_idx_bkg[BB*KTOP];
__device__ float g_actmean[BB*CC];

// ============================================================
// K1: fused  cas = (x*mask)@W^T,  mag = ||x||,  features copy,
//            cas_softmax epilogue.
// Block: 256 threads = 32 rows x 8 f-lanes. F chunked by 128,
// W chunk staged in smem (10KB), broadcast across rows.
// ============================================================
constexpr int TM   = 32;
constexpr int TPB1 = 256;
constexpr int CF   = 128;

__global__ __launch_bounds__(TPB1) void k1_main(
    const float* __restrict__ x, const float* __restrict__ W,
    const float* __restrict__ m, float* __restrict__ out)
{
    __shared__ float sW[CC*CF];            // 10 KB
    const int tid = threadIdx.x;
    const int r = tid >> 3, j = tid & 7;
    const int row = blockIdx.x * TM + r;   // < 12000

    const float4* __restrict__ x4 = (const float4*)x;
    const float4* __restrict__ m4 = (const float4*)m;
    float4* __restrict__ f4 = (float4*)(out + OFF_FEAT);

    float acc[CC];
#pragma unroll
    for (int c = 0; c < CC; c++) acc[c] = 0.f;
    float ss = 0.f;

    for (int ch = 0; ch < FF/CF; ch++) {
        __syncthreads();
        for (int k = tid; k < CC*CF; k += TPB1)
            sW[k] = W[(k >> 7) * FF + ch*CF + (k & 127)];
        __syncthreads();
        const float4* sW4 = (const float4*)sW;
#pragma unroll
        for (int i = 0; i < 4; i++) {
            int gi = row * (FF/4) + ch * (CF/4) + i*8 + j;
            float4 xv = x4[gi];
            float4 mv = m4[gi];
            f4[gi] = xv;                                   // features output
            float4 xm = make_float4(xv.x*mv.x, xv.y*mv.y, xv.z*mv.z, xv.w*mv.w);
            ss += xv.x*xv.x + xv.y*xv.y + xv.z*xv.z + xv.w*xv.w;
#pragma unroll
            for (int c = 0; c < CC; c++) {
                float4 wv = sW4[c * (CF/4) + i*8 + j];
                acc[c] += xm.x*wv.x + xm.y*wv.y + xm.z*wv.z + xm.w*wv.w;
            }
        }
    }

    // reduce over the 8 f-lanes of this row (aligned 8-lane groups in warp)
#pragma unroll
    for (int c = 0; c < CC; c++) {
        acc[c] += __shfl_down_sync(0xffffffffu, acc[c], 4, 8);
        acc[c] += __shfl_down_sync(0xffffffffu, acc[c], 2, 8);
        acc[c] += __shfl_down_sync(0xffffffffu, acc[c], 1, 8);
    }
    ss += __shfl_down_sync(0xffffffffu, ss, 4, 8);
    ss += __shfl_down_sync(0xffffffffu, ss, 2, 8);
    ss += __shfl_down_sync(0xffffffffu, ss, 1, 8);

    if (j == 0) {
        g_mag[row] = sqrtf(ss);
        float mx = acc[0];
#pragma unroll
        for (int c = 1; c < CC; c++) mx = fmaxf(mx, acc[c]);
        float e[CC]; float s = 0.f;
#pragma unroll
        for (int c = 0; c < CC; c++) { e[c] = expf(acc[c] - mx); s += e[c]; }
        float inv = 1.f / s;
#pragma unroll
        for (int c = 0; c < CC; c++) {
            g_cas[row*CC + c] = acc[c];
            out[OFF_CSM + row*CC + c] = e[c] * inv;        // cas_softmax
        }
    }
}

// ============================================================
// K2a: per-batch. magmax, stable top-k (rank = #greater +
// #equal-with-smaller-index, matching jax.lax.top_k), score_bkg.
// ============================================================
constexpr int TPB2 = 768;

__global__ __launch_bounds__(TPB2) void k2_topk(
    const float* __restrict__ sel, float* __restrict__ out)
{
    __shared__ float s_mag[TT], s_md[TT], s_rd[TT];
    __shared__ float s_red[TPB2/32];
    __shared__ float s_sum[CC];
    const int b = blockIdx.x, tid = threadIdx.x;

    for (int t = tid; t < TT; t += TPB2) s_mag[t] = g_mag[b*TT + t];
    __syncthreads();

    float mx = -1.f;
    for (int t = tid; t < TT; t += TPB2) mx = fmaxf(mx, s_mag[t]);
#pragma unroll
    for (int o = 16; o > 0; o >>= 1) mx = fmaxf(mx, __shfl_down_sync(0xffffffffu, mx, o));
    if ((tid & 31) == 0) s_red[tid >> 5] = mx;
    __syncthreads();
    if (tid == 0) {
        float mm = s_red[0];
        for (int w = 1; w < TPB2/32; w++) mm = fmaxf(mm, s_red[w]);
        s_red[0] = mm;
    }
    __syncthreads();
    const float magmax = s_red[0];

    for (int t = tid; t < TT; t += TPB2) {
        float sl = sel[b*TT + t];
        s_md[t] = s_mag[t] * sl;
        s_rd[t] = (magmax - s_mag[t]) * sl;
    }
    __syncthreads();

    for (int t = tid; t < TT; t += TPB2) {
        float v = s_md[t]; int rank = 0;
        for (int u = 0; u < TT; u++) {
            float w = s_md[u];
            rank += (w > v) || (w == v && u < t);
        }
        if (rank < KTOP) g_idx_act[b*KTOP + rank] = t;

        float v2 = s_rd[t]; int rank2 = 0;
        for (int u = 0; u < TT; u++) {
            float w = s_rd[u];
            rank2 += (w > v2) || (w == v2 && u < t);
        }
        if (rank2 < KTOP) g_idx_bkg[b*KTOP + rank2] = t;
    }
    __syncthreads();

    // score_bkg = softmax_C( mean over idx_bkg of cas )
    if (tid < CC) {
        float s = 0.f;
        for (int i = 0; i < KTOP; i++) {
            int t = g_idx_bkg[b*KTOP + i];
            s += g_cas[(b*TT + t)*CC + tid];
        }
        s_sum[tid] = s * (1.f / KTOP);
    }
    __syncthreads();
    if (tid < CC) {
        float mxv = s_sum[0];
        for (int c = 1; c < CC; c++) mxv = fmaxf(mxv, s_sum[c]);
        float tot = 0.f;
        for (int c = 0; c < CC; c++) tot += expf(s_sum[c] - mxv);
        out[OFF_SBKG + b*CC + tid] = expf(s_sum[tid] - mxv) / tot;
    }
}

// ============================================================
// K2b: per (b,c) block — mean of top-93 of cas[b,:,c]
// ============================================================
__global__ __launch_bounds__(256) void k2_actmean()
{
    __shared__ float s_v[TT];
    __shared__ float s_part[256];
    const int b = blockIdx.x, c = blockIdx.y, tid = threadIdx.x;

    for (int t = tid; t < TT; t += 256) s_v[t] = g_cas[(b*TT + t)*CC + c];
    __syncthreads();

    float local = 0.f;
    for (int t = tid; t < TT; t += 256) {
        float v = s_v[t]; int rank = 0;
        for (int u = 0; u < TT; u++) {
            float w = s_v[u];
            rank += (w > v) || (w == v && u < t);
        }
        if (rank < KTOP) local += v;
    }
    s_part[tid] = local;
    __syncthreads();
    for (int s = 128; s > 0; s >>= 1) {
        if (tid < s) s_part[tid] += s_part[tid + s];
        __syncthreads();
    }
    if (tid == 0) g_actmean[b*CC + c] = s_part[0] * (1.f / KTOP);
}

// K2c: softmax over C of actmean -> score_act
__global__ void k2_actsoftmax(float* __restrict__ out)
{
    int i = threadIdx.x;            // BB*CC = 320 threads
    int b = i / CC, c = i % CC;
    float mxv = g_actmean[b*CC];
    for (int k = 1; k < CC; k++) mxv = fmaxf(mxv, g_actmean[b*CC + k]);
    float s = 0.f;
    for (int k = 0; k < CC; k++) s += expf(g_actmean[b*CC + k] - mxv);
    out[OFF_SACT + i] = expf(g_actmean[b*CC + c] - mxv) / s;
}

// ============================================================
// K3: gather feat_act / feat_bkg rows from x
// ============================================================
__global__ __launch_bounds__(256) void k3_gather(
    const float* __restrict__ x, float* __restrict__ out)
{
    const int blk = blockIdx.x;                 // 2*B*KTOP blocks
    const int which = blk / (BB*KTOP);          // 0=act, 1=bkg
    const int rem = blk % (BB*KTOP);
    const int b = rem / KTOP, i = rem % KTOP;
    const int t = which ? g_idx_bkg[b*KTOP + i] : g_idx_act[b*KTOP + i];
    const float4* __restrict__ src = (const float4*)(x + (size_t)(b*TT + t) * FF);
    float4* __restrict__ dst =
        (float4*)(out + (which ? OFF_FBKG : OFF_FACT) + (size_t)rem * FF);
#pragma unroll 4
    for (int k = threadIdx.x; k < FF/4; k += 256) dst[k] = src[k];
}

// ============================================================
extern "C" void kernel_launch(void* const* d_in, const int* in_sizes, int n_in,
                              void* d_out, int out_size)
{
    const float *x = nullptr, *W = nullptr, *m = nullptr, *sel = nullptr;
    for (int i = 0; i < n_in; i++) {
        if (in_sizes[i] == CC*FF)            W   = (const float*)d_in[i];
        else if (in_sizes[i] == BB*TT)       sel = (const float*)d_in[i];
        else if (in_sizes[i] == BB*TT*FF) {
            if (!x) x = (const float*)d_in[i];
            else    m = (const float*)d_in[i];
        }
    }
    float* out = (float*)d_out;

    k1_main<<<ROWS/TM, TPB1>>>(x, W, m, out);
    k2_topk<<<BB, TPB2>>>(sel, out);
    dim3 g2(BB, CC);
    k2_actmean<<<g2, 256>>>();
    k2_actsoftmax<<<1, BB*CC>>>(out);
    k3_gather<<<2*BB*KTOP, 256>>>(x, out);
}

// round 2
// speedup vs baseline: 1.1165x; 1.1165x over previous
#include <cuda_runtime.h>
#include <math.h>

#define BB 16
#define TT 750
#define FF 4096
#define CC 20
#define KTOP 93
#define ROWS (BB*TT)

// ---- output layout (flattened tuple, reference return order) ----
#define OFF_SACT 0
#define OFF_SBKG (BB*CC)
#define OFF_FACT (2*BB*CC)
#define OFF_FBKG (OFF_FACT + BB*KTOP*FF)
#define OFF_FEAT (OFF_FBKG + BB*KTOP*FF)
#define OFF_CSM  (OFF_FEAT + ROWS*FF)

// ---- scratch ----
__device__ float g_cas[ROWS*CC];
__device__ float g_mag[ROWS];
__device__ int   g_idx_act[BB*KTOP];
__device__ int   g_idx_bkg[BB*KTOP];
__device__ float g_actmean[BB*CC];

// ---- f32x2 packed helpers (sm_103a FFMA2 path, PTX-only) ----
__device__ __forceinline__ unsigned long long pk2(float lo, float hi) {
    unsigned long long r;
    asm("mov.b64 %0, {%1,%2};" : "=l"(r) : "f"(lo), "f"(hi));
    return r;
}
__device__ __forceinline__ void upk2(unsigned long long v, float& lo, float& hi) {
    asm("mov.b64 {%0,%1}, %2;" : "=f"(lo), "=f"(hi) : "l"(v));
}
__device__ __forceinline__ void ffma2(unsigned long long& acc,
                                      unsigned long long a, unsigned long long b) {
    asm("fma.rn.f32x2 %0, %1, %2, %0;" : "+l"(acc) : "l"(a), "l"(b));
}
__device__ __forceinline__ unsigned long long mul2(unsigned long long a,
                                                   unsigned long long b) {
    unsigned long long r;
    asm("mul.rn.f32x2 %0, %1, %2;" : "=l"(r) : "l"(a), "l"(b));
    return r;
}

// ============================================================
// K1: fused  cas = (x*mask)@W^T,  mag = ||x||,  features copy,
//            cas_softmax epilogue.
// 128 threads = 16 row-groups x 8 f-lanes; 2 rows per thread
// (W smem loads amortized over 2 rows); f32x2 packed FFMA.
// ============================================================
constexpr int TPB1 = 128;
constexpr int RPT  = 2;
constexpr int TM   = 32;           // rows per block
constexpr int CF   = 128;          // F-chunk

__global__ __launch_bounds__(TPB1) void k1_main(
    const float* __restrict__ x, const float* __restrict__ W,
    const float* __restrict__ m, float* __restrict__ out)
{
    __shared__ float sW[CC*CF];    // 10 KB
    const int tid = threadIdx.x;
    const int r = tid >> 3, j = tid & 7;
    const int row0 = blockIdx.x * TM + r * RPT;

    const float4* __restrict__ x4 = (const float4*)x;
    const float4* __restrict__ m4 = (const float4*)m;
    float4* __restrict__ f4 = (float4*)(out + OFF_FEAT);

    unsigned long long acc2[RPT][CC];
    unsigned long long ss2[RPT];
#pragma unroll
    for (int k = 0; k < RPT; k++) {
        ss2[k] = 0ull;
#pragma unroll
        for (int c = 0; c < CC; c++) acc2[k][c] = 0ull;
    }

    for (int ch = 0; ch < FF/CF; ch++) {
        __syncthreads();
#pragma unroll
        for (int k = tid; k < CC*CF; k += TPB1)
            sW[k] = W[(k >> 7) * FF + ch*CF + (k & 127)];
        __syncthreads();
        const float4* sW4 = (const float4*)sW;

#pragma unroll
        for (int i = 0; i < 4; i++) {
            unsigned long long xm01[RPT], xm23[RPT];
#pragma unroll
            for (int k = 0; k < RPT; k++) {
                int gi = (row0 + k) * (FF/4) + ch * (CF/4) + i*8 + j;
                float4 xv = x4[gi];
                float4 mv = m4[gi];
                f4[gi] = xv;                                  // features copy
                unsigned long long x01 = pk2(xv.x, xv.y);
                unsigned long long x23 = pk2(xv.z, xv.w);
                ffma2(ss2[k], x01, x01);
                ffma2(ss2[k], x23, x23);
                xm01[k] = mul2(x01, pk2(mv.x, mv.y));
                xm23[k] = mul2(x23, pk2(mv.z, mv.w));
            }
#pragma unroll
            for (int c = 0; c < CC; c++) {
                float4 wv = sW4[c * (CF/4) + i*8 + j];
                unsigned long long w01 = pk2(wv.x, wv.y);
                unsigned long long w23 = pk2(wv.z, wv.w);
#pragma unroll
                for (int k = 0; k < RPT; k++) {
                    ffma2(acc2[k][c], xm01[k], w01);
                    ffma2(acc2[k][c], xm23[k], w23);
                }
            }
        }
    }

#pragma unroll
    for (int k = 0; k < RPT; k++) {
        float acc[CC];
#pragma unroll
        for (int c = 0; c < CC; c++) {
            float lo, hi; upk2(acc2[k][c], lo, hi);
            acc[c] = lo + hi;
            acc[c] += __shfl_down_sync(0xffffffffu, acc[c], 4, 8);
            acc[c] += __shfl_down_sync(0xffffffffu, acc[c], 2, 8);
            acc[c] += __shfl_down_sync(0xffffffffu, acc[c], 1, 8);
        }
        float slo, shi; upk2(ss2[k], slo, shi);
        float ss = slo + shi;
        ss += __shfl_down_sync(0xffffffffu, ss, 4, 8);
        ss += __shfl_down_sync(0xffffffffu, ss, 2, 8);
        ss += __shfl_down_sync(0xffffffffu, ss, 1, 8);

        if (j == 0) {
            int row = row0 + k;
            g_mag[row] = sqrtf(ss);
            float mx = acc[0];
#pragma unroll
            for (int c = 1; c < CC; c++) mx = fmaxf(mx, acc[c]);
            float e[CC]; float s = 0.f;
#pragma unroll
            for (int c = 0; c < CC; c++) { e[c] = expf(acc[c] - mx); s += e[c]; }
            float inv = 1.f / s;
#pragma unroll
            for (int c = 0; c < CC; c++) {
                g_cas[row*CC + c] = acc[c];
                out[OFF_CSM + row*CC + c] = e[c] * inv;
            }
        }
    }
}

// ============================================================
// K2a: per-batch. magmax, stable top-k (jax.lax.top_k semantics),
// score_bkg.
// ============================================================
constexpr int TPB2 = 768;

__global__ __launch_bounds__(TPB2) void k2_topk(
    const float* __restrict__ sel, float* __restrict__ out)
{
    __shared__ float s_mag[TT], s_md[TT], s_rd[TT];
    __shared__ float s_red[TPB2/32];
    __shared__ float s_sum[CC];
    const int b = blockIdx.x, tid = threadIdx.x;

    for (int t = tid; t < TT; t += TPB2) s_mag[t] = g_mag[b*TT + t];
    __syncthreads();

    float mx = -1.f;
    for (int t = tid; t < TT; t += TPB2) mx = fmaxf(mx, s_mag[t]);
#pragma unroll
    for (int o = 16; o > 0; o >>= 1) mx = fmaxf(mx, __shfl_down_sync(0xffffffffu, mx, o));
    if ((tid & 31) == 0) s_red[tid >> 5] = mx;
    __syncthreads();
    if (tid == 0) {
        float mm = s_red[0];
        for (int w = 1; w < TPB2/32; w++) mm = fmaxf(mm, s_red[w]);
        s_red[0] = mm;
    }
    __syncthreads();
    const float magmax = s_red[0];

    for (int t = tid; t < TT; t += TPB2) {
        float sl = sel[b*TT + t];
        s_md[t] = s_mag[t] * sl;
        s_rd[t] = (magmax - s_mag[t]) * sl;
    }
    __syncthreads();

    for (int t = tid; t < TT; t += TPB2) {
        float v = s_md[t]; int rank = 0;
        for (int u = 0; u < TT; u++) {
            float w = s_md[u];
            rank += (w > v) || (w == v && u < t);
        }
        if (rank < KTOP) g_idx_act[b*KTOP + rank] = t;

        float v2 = s_rd[t]; int rank2 = 0;
        for (int u = 0; u < TT; u++) {
            float w = s_rd[u];
            rank2 += (w > v2) || (w == v2 && u < t);
        }
        if (rank2 < KTOP) g_idx_bkg[b*KTOP + rank2] = t;
    }
    __syncthreads();

    if (tid < CC) {
        float s = 0.f;
        for (int i = 0; i < KTOP; i++) {
            int t = g_idx_bkg[b*KTOP + i];
            s += g_cas[(b*TT + t)*CC + tid];
        }
        s_sum[tid] = s * (1.f / KTOP);
    }
    __syncthreads();
    if (tid < CC) {
        float mxv = s_sum[0];
        for (int c = 1; c < CC; c++) mxv = fmaxf(mxv, s_sum[c]);
        float tot = 0.f;
        for (int c = 0; c < CC; c++) tot += expf(s_sum[c] - mxv);
        out[OFF_SBKG + b*CC + tid] = expf(s_sum[tid] - mxv) / tot;
    }
}

// ============================================================
// K2b: per (b,c) block — mean of top-93 of cas[b,:,c]
// ============================================================
__global__ __launch_bounds__(256) void k2_actmean()
{
    __shared__ float s_v[TT];
    __shared__ float s_part[256];
    const int b = blockIdx.x, c = blockIdx.y, tid = threadIdx.x;

    for (int t = tid; t < TT; t += 256) s_v[t] = g_cas[(b*TT + t)*CC + c];
    __syncthreads();

    float local = 0.f;
    for (int t = tid; t < TT; t += 256) {
        float v = s_v[t]; int rank = 0;
        for (int u = 0; u < TT; u++) {
            float w = s_v[u];
            rank += (w > v) || (w == v && u < t);
        }
        if (rank < KTOP) local += v;
    }
    s_part[tid] = local;
    __syncthreads();
    for (int s = 128; s > 0; s >>= 1) {
        if (tid < s) s_part[tid] += s_part[tid + s];
        __syncthreads();
    }
    if (tid == 0) g_actmean[b*CC + c] = s_part[0] * (1.f / KTOP);
}

// K2c: softmax over C of actmean -> score_act
__global__ void k2_actsoftmax(float* __restrict__ out)
{
    int i = threadIdx.x;            // BB*CC = 320 threads
    int b = i / CC, c = i % CC;
    float mxv = g_actmean[b*CC];
    for (int k = 1; k < CC; k++) mxv = fmaxf(mxv, g_actmean[b*CC + k]);
    float s = 0.f;
    for (int k = 0; k < CC; k++) s += expf(g_actmean[b*CC + k] - mxv);
    out[OFF_SACT + i] = expf(g_actmean[b*CC + c] - mxv) / s;
}

// ============================================================
// K3: gather feat_act / feat_bkg rows from x
// ============================================================
__global__ __launch_bounds__(256) void k3_gather(
    const float* __restrict__ x, float* __restrict__ out)
{
    const int blk = blockIdx.x;                 // 2*B*KTOP blocks
    const int which = blk / (BB*KTOP);          // 0=act, 1=bkg
    const int rem = blk % (BB*KTOP);
    const int b = rem / KTOP, i = rem % KTOP;
    const int t = which ? g_idx_bkg[b*KTOP + i] : g_idx_act[b*KTOP + i];
    const float4* __restrict__ src = (const float4*)(x + (size_t)(b*TT + t) * FF);
    float4* __restrict__ dst =
        (float4*)(out + (which ? OFF_FBKG : OFF_FACT) + (size_t)rem * FF);
#pragma unroll 4
    for (int k = threadIdx.x; k < FF/4; k += 256) dst[k] = src[k];
}

// ============================================================
extern "C" void kernel_launch(void* const* d_in, const int* in_sizes, int n_in,
                              void* d_out, int out_size)
{
    const float *x = nullptr, *W = nullptr, *m = nullptr, *sel = nullptr;
    for (int i = 0; i < n_in; i++) {
        if (in_sizes[i] == CC*FF)            W   = (const float*)d_in[i];
        else if (in_sizes[i] == BB*TT)       sel = (const float*)d_in[i];
        else if (in_sizes[i] == BB*TT*FF) {
            if (!x) x = (const float*)d_in[i];
            else    m = (const float*)d_in[i];
        }
    }
    float* out = (float*)d_out;

    k1_main<<<ROWS/TM, TPB1>>>(x, W, m, out);
    k2_topk<<<BB, TPB2>>>(sel, out);
    dim3 g2(BB, CC);
    k2_actmean<<<g2, 256>>>();
    k2_actsoftmax<<<1, BB*CC>>>(out);
    k3_gather<<<2*BB*KTOP, 256>>>(x, out);
}

// round 3
// speedup vs baseline: 1.2245x; 1.0968x over previous
#include <cuda_runtime.h>
#include <math.h>

#define BB 16
#define TT 750
#define FF 4096
#define CC 20
#define KTOP 93
#define ROWS (BB*TT)

// ---- output layout (flattened tuple, reference return order) ----
#define OFF_SACT 0
#define OFF_SBKG (BB*CC)
#define OFF_FACT (2*BB*CC)
#define OFF_FBKG (OFF_FACT + BB*KTOP*FF)
#define OFF_FEAT (OFF_FBKG + BB*KTOP*FF)
#define OFF_CSM  (OFF_FEAT + ROWS*FF)

// ---- scratch ----
__device__ float g_cas[ROWS*CC];
__device__ float g_mag[ROWS];
__device__ int   g_idx_act[BB*KTOP];
__device__ int   g_idx_bkg[BB*KTOP];
__device__ float g_actmean[BB*CC];

// ============================================================
// K1: fused  cas = (x*mask)@W^T,  mag = ||x||,  features copy,
//            cas_softmax epilogue.
// 128 thr = 16 row-groups x 8 f-lanes, 2 rows/thread.
// Per chunk: ALL 16 x/m LDG.128 issued up front (max MLP),
// W double-buffered in smem with register prefetch.
// ============================================================
constexpr int TPB1 = 128;
constexpr int TM   = 32;           // rows per block
constexpr int CF   = 128;          // F-chunk floats
constexpr int NCH  = FF/CF;        // 32 chunks

__global__ __launch_bounds__(TPB1) void k1_main(
    const float* __restrict__ x, const float* __restrict__ W,
    const float* __restrict__ m, float* __restrict__ out)
{
    __shared__ float sW[2][CC*CF];         // 2 x 10 KB
    const int tid = threadIdx.x;
    const int j = tid & 7;                  // f-lane
    const int g = tid >> 3;                 // row-group 0..15
    const int row0 = blockIdx.x * TM + g * 2;

    const float4* __restrict__ x4 = (const float4*)x;
    const float4* __restrict__ m4 = (const float4*)m;
    float4* __restrict__ f4 = (float4*)(out + OFF_FEAT);

    float acc[2][CC];
#pragma unroll
    for (int k = 0; k < 2; k++)
#pragma unroll
        for (int c = 0; c < CC; c++) acc[k][c] = 0.f;
    float ss[2] = {0.f, 0.f};

    // prologue: stage W chunk 0 into buffer 0
    // thread tid loads column `tid` of class t  (t = 0..19)
    {
        float wpre[CC];
#pragma unroll
        for (int t = 0; t < CC; t++) wpre[t] = W[t*FF + tid];
#pragma unroll
        for (int t = 0; t < CC; t++) sW[0][t*CF + tid] = wpre[t];
    }
    __syncthreads();

    for (int ch = 0; ch < NCH; ch++) {
        const int buf = ch & 1;

        // ---- kick W prefetch for next chunk (L2-resident) ----
        float wpre[CC];
        if (ch + 1 < NCH) {
#pragma unroll
            for (int t = 0; t < CC; t++)
                wpre[t] = W[t*FF + (ch+1)*CF + tid];
        }

        // ---- issue ALL x/m loads for this chunk (16 LDG.128) ----
        float4 xv[2][4], mv[2][4];
#pragma unroll
        for (int k = 0; k < 2; k++)
#pragma unroll
            for (int i = 0; i < 4; i++) {
                int gi = (row0 + k) * (FF/4) + ch * (CF/4) + i*8 + j;
                xv[k][i] = x4[gi];
                mv[k][i] = m4[gi];
            }

        // ---- features copy + sum-of-squares + apply mask ----
#pragma unroll
        for (int k = 0; k < 2; k++)
#pragma unroll
            for (int i = 0; i < 4; i++) {
                int gi = (row0 + k) * (FF/4) + ch * (CF/4) + i*8 + j;
                float4 v = xv[k][i];
                f4[gi] = v;
                ss[k] += v.x*v.x + v.y*v.y + v.z*v.z + v.w*v.w;
                float4 mm = mv[k][i];
                xv[k][i] = make_float4(v.x*mm.x, v.y*mm.y, v.z*mm.z, v.w*mm.w);
            }

        // ---- FFMA over classes (smem broadcast reads) ----
        const float4* sW4 = (const float4*)sW[buf];
#pragma unroll
        for (int c = 0; c < CC; c++) {
#pragma unroll
            for (int i = 0; i < 4; i++) {
                float4 wv = sW4[c * (CF/4) + i*8 + j];
                float a = acc[0][c];
                float b = acc[1][c];
                a += xv[0][i].x*wv.x + xv[0][i].y*wv.y + xv[0][i].z*wv.z + xv[0][i].w*wv.w;
                b += xv[1][i].x*wv.x + xv[1][i].y*wv.y + xv[1][i].z*wv.z + xv[1][i].w*wv.w;
                acc[0][c] = a;
                acc[1][c] = b;
            }
        }

        // ---- commit W prefetch into the other buffer ----
        if (ch + 1 < NCH) {
#pragma unroll
            for (int t = 0; t < CC; t++) sW[buf ^ 1][t*CF + tid] = wpre[t];
        }
        __syncthreads();
    }

    // ---- reduce 8 f-lanes per row, epilogue ----
#pragma unroll
    for (int k = 0; k < 2; k++) {
#pragma unroll
        for (int c = 0; c < CC; c++) {
            float a = acc[k][c];
            a += __shfl_down_sync(0xffffffffu, a, 4, 8);
            a += __shfl_down_sync(0xffffffffu, a, 2, 8);
            a += __shfl_down_sync(0xffffffffu, a, 1, 8);
            acc[k][c] = a;
        }
        float s = ss[k];
        s += __shfl_down_sync(0xffffffffu, s, 4, 8);
        s += __shfl_down_sync(0xffffffffu, s, 2, 8);
        s += __shfl_down_sync(0xffffffffu, s, 1, 8);

        if (j == 0) {
            int row = row0 + k;
            g_mag[row] = sqrtf(s);
            float mx = acc[k][0];
#pragma unroll
            for (int c = 1; c < CC; c++) mx = fmaxf(mx, acc[k][c]);
            float e[CC]; float tot = 0.f;
#pragma unroll
            for (int c = 0; c < CC; c++) { e[c] = expf(acc[k][c] - mx); tot += e[c]; }
            float inv = 1.f / tot;
#pragma unroll
            for (int c = 0; c < CC; c++) {
                g_cas[row*CC + c] = acc[k][c];
                out[OFF_CSM + row*CC + c] = e[c] * inv;
            }
        }
    }
}

// ============================================================
// K2a: per-batch. magmax, stable top-k (jax.lax.top_k semantics),
// score_bkg.
// ============================================================
constexpr int TPB2 = 768;

__global__ __launch_bounds__(TPB2) void k2_topk(
    const float* __restrict__ sel, float* __restrict__ out)
{
    __shared__ float s_mag[TT], s_md[TT], s_rd[TT];
    __shared__ float s_red[TPB2/32];
    __shared__ float s_sum[CC];
    const int b = blockIdx.x, tid = threadIdx.x;

    for (int t = tid; t < TT; t += TPB2) s_mag[t] = g_mag[b*TT + t];
    __syncthreads();

    float mx = -1.f;
    for (int t = tid; t < TT; t += TPB2) mx = fmaxf(mx, s_mag[t]);
#pragma unroll
    for (int o = 16; o > 0; o >>= 1) mx = fmaxf(mx, __shfl_down_sync(0xffffffffu, mx, o));
    if ((tid & 31) == 0) s_red[tid >> 5] = mx;
    __syncthreads();
    if (tid == 0) {
        float mm = s_red[0];
        for (int w = 1; w < TPB2/32; w++) mm = fmaxf(mm, s_red[w]);
        s_red[0] = mm;
    }
    __syncthreads();
    const float magmax = s_red[0];

    for (int t = tid; t < TT; t += TPB2) {
        float sl = sel[b*TT + t];
        s_md[t] = s_mag[t] * sl;
        s_rd[t] = (magmax - s_mag[t]) * sl;
    }
    __syncthreads();

    for (int t = tid; t < TT; t += TPB2) {
        float v = s_md[t]; int rank = 0;
        for (int u = 0; u < TT; u++) {
            float w = s_md[u];
            rank += (w > v) || (w == v && u < t);
        }
        if (rank < KTOP) g_idx_act[b*KTOP + rank] = t;

        float v2 = s_rd[t]; int rank2 = 0;
        for (int u = 0; u < TT; u++) {
            float w = s_rd[u];
            rank2 += (w > v2) || (w == v2 && u < t);
        }
        if (rank2 < KTOP) g_idx_bkg[b*KTOP + rank2] = t;
    }
    __syncthreads();

    if (tid < CC) {
        float s = 0.f;
        for (int i = 0; i < KTOP; i++) {
            int t = g_idx_bkg[b*KTOP + i];
            s += g_cas[(b*TT + t)*CC + tid];
        }
        s_sum[tid] = s * (1.f / KTOP);
    }
    __syncthreads();
    if (tid < CC) {
        float mxv = s_sum[0];
        for (int c = 1; c < CC; c++) mxv = fmaxf(mxv, s_sum[c]);
        float tot = 0.f;
        for (int c = 0; c < CC; c++) tot += expf(s_sum[c] - mxv);
        out[OFF_SBKG + b*CC + tid] = expf(s_sum[tid] - mxv) / tot;
    }
}

// ============================================================
// K2b: per (b,c) block — mean of top-93 of cas[b,:,c]
// ============================================================
__global__ __launch_bounds__(256) void k2_actmean()
{
    __shared__ float s_v[TT];
    __shared__ float s_part[256];
    const int b = blockIdx.x, c = blockIdx.y, tid = threadIdx.x;

    for (int t = tid; t < TT; t += 256) s_v[t] = g_cas[(b*TT + t)*CC + c];
    __syncthreads();

    float local = 0.f;
    for (int t = tid; t < TT; t += 256) {
        float v = s_v[t]; int rank = 0;
        for (int u = 0; u < TT; u++) {
            float w = s_v[u];
            rank += (w > v) || (w == v && u < t);
        }
        if (rank < KTOP) local += v;
    }
    s_part[tid] = local;
    __syncthreads();
    for (int s = 128; s > 0; s >>= 1) {
        if (tid < s) s_part[tid] += s_part[tid + s];
        __syncthreads();
    }
    if (tid == 0) g_actmean[b*CC + c] = s_part[0] * (1.f / KTOP);
}

// ============================================================
// K3: gather feat_act / feat_bkg rows; last block does the
// score_act softmax (reads g_actmean from k2_actmean).
// ============================================================
__global__ __launch_bounds__(256) void k3_gather(
    const float* __restrict__ x, float* __restrict__ out)
{
    const int blk = blockIdx.x;
    if (blk == 2*BB*KTOP) {                     // extra block: score_act softmax
#pragma unroll
        for (int i = threadIdx.x; i < BB*CC; i += 256) {
            int b = i / CC, c = i % CC;
            float mxv = g_actmean[b*CC];
            for (int k = 1; k < CC; k++) mxv = fmaxf(mxv, g_actmean[b*CC + k]);
            float s = 0.f;
            for (int k = 0; k < CC; k++) s += expf(g_actmean[b*CC + k] - mxv);
            out[OFF_SACT + i] = expf(g_actmean[b*CC + c] - mxv) / s;
        }
        return;
    }
    const int which = blk / (BB*KTOP);          // 0=act, 1=bkg
    const int rem = blk % (BB*KTOP);
    const int b = rem / KTOP, i = rem % KTOP;
    const int t = which ? g_idx_bkg[b*KTOP + i] : g_idx_act[b*KTOP + i];
    const float4* __restrict__ src = (const float4*)(x + (size_t)(b*TT + t) * FF);
    float4* __restrict__ dst =
        (float4*)(out + (which ? OFF_FBKG : OFF_FACT) + (size_t)rem * FF);
#pragma unroll 4
    for (int k = threadIdx.x; k < FF/4; k += 256) dst[k] = src[k];
}

// ============================================================
extern "C" void kernel_launch(void* const* d_in, const int* in_sizes, int n_in,
                              void* d_out, int out_size)
{
    const float *x = nullptr, *W = nullptr, *m = nullptr, *sel = nullptr;
    for (int i = 0; i < n_in; i++) {
        if (in_sizes[i] == CC*FF)            W   = (const float*)d_in[i];
        else if (in_sizes[i] == BB*TT)       sel = (const float*)d_in[i];
        else if (in_sizes[i] == BB*TT*FF) {
            if (!x) x = (const float*)d_in[i];
            else    m = (const float*)d_in[i];
        }
    }
    float* out = (float*)d_out;

    k1_main<<<ROWS/TM, TPB1>>>(x, W, m, out);
    k2_topk<<<BB, TPB2>>>(sel, out);
    dim3 g2(BB, CC);
    k2_actmean<<<g2, 256>>>();
    k3_gather<<<2*BB*KTOP + 1, 256>>>(x, out);
}